// round 5
// baseline (speedup 1.0000x reference)
#include <cuda_runtime.h>
#include <cstdint>
#include <cstddef>

// ---------------------------------------------------------------------------
// GATv2 x3 layers.  Dims: 4 -> 128 -> 512 -> 1028, H=32 heads, head-mean.
//   GEMMs: mma.sync.m16n8k8 tf32 (sm_103 baseline; tcgen05 unavailable),
//     128x128 CTA tile, 4 warps x (64x64), BK=32, cp.async double buffer.
//     Epilogue writes HEAD-MAJOR scratch xl/xr: [h][n][c]  (L2-friendly).
//   Edge phase: block per dst node, all heads looped in-register.
//     No atomics, no zero pass; bias + leaky fused into epilogue.
// ---------------------------------------------------------------------------

#define MAX_N 10000
#define MAX_E 160000
#define MAX_EL (MAX_E + MAX_N)

// scratch (allocation-free rule: __device__ globals)
__device__ float g_xl[328960000];          // 10000 * 32 * 1028
__device__ float g_xr[328960000];
__device__ float g_h1[MAX_N * 128];
__device__ float g_h2[MAX_N * 512];
__device__ int   g_deg[MAX_N];
__device__ int   g_rowptr[MAX_N + 1];
__device__ int   g_cursor[MAX_N];
__device__ int   g_col[MAX_EL];

// ---------------------------------------------------------------------------
// mma.sync tf32 GEMM
// ---------------------------------------------------------------------------
#define AS_STRIDE 36   // floats per A smem row  (128 rows)
#define BS_STRIDE 136  // floats per B smem row  (32 rows)
#define AS_BYTES (128 * AS_STRIDE * 4)   // 18432
#define BS_BYTES (32 * BS_STRIDE * 4)    // 17408
#define GEMM_SMEM (2 * (AS_BYTES + BS_BYTES))  // 71680

__device__ __forceinline__ void cp16(uint32_t dst, const void* src, int bytes) {
    asm volatile("cp.async.cg.shared.global [%0], [%1], 16, %2;"
                 :: "r"(dst), "l"(src), "r"(bytes) : "memory");
}
__device__ __forceinline__ void cp_commit() {
    asm volatile("cp.async.commit_group;" ::: "memory");
}
template <int N>
__device__ __forceinline__ void cp_wait() {
    asm volatile("cp.async.wait_group %0;" :: "n"(N) : "memory");
}
__device__ __forceinline__ uint32_t smem_u32(const void* p) {
    uint32_t a;
    asm("{ .reg .u64 t; cvta.to.shared.u64 t, %1; cvt.u32.u64 %0, t; }"
        : "=r"(a) : "l"(p));
    return a;
}
__device__ __forceinline__ uint32_t f2tf32(float x) {
    uint32_t u;
    asm("cvt.rna.tf32.f32 %0, %1;" : "=r"(u) : "f"(x));
    return u;
}
__device__ __forceinline__ void mma_tf32(float& c0, float& c1, float& c2, float& c3,
                                         uint32_t a0, uint32_t a1, uint32_t a2, uint32_t a3,
                                         uint32_t b0, uint32_t b1) {
    asm volatile(
        "mma.sync.aligned.m16n8k8.row.col.f32.tf32.tf32.f32 "
        "{%0,%1,%2,%3}, {%4,%5,%6,%7}, {%8,%9}, {%0,%1,%2,%3};"
        : "+f"(c0), "+f"(c1), "+f"(c2), "+f"(c3)
        : "r"(a0), "r"(a1), "r"(a2), "r"(a3), "r"(b0), "r"(b1));
}

// C_out[h][m][c] = (A[M,K] @ B[K,H*C])[m, h*C+c] + bias[h*C+c]
// Head-major output:  out[((h * Mn) + m) * C + c].  Ncols % 128 == 0, K % 4 == 0.
__global__ __launch_bounds__(128, 2) void gemm_mma_k(
    const float* __restrict__ A, const float* __restrict__ B,
    const float* __restrict__ bias, float* __restrict__ Cmat,
    int M, int K, int Ncols, int Cdim)
{
    extern __shared__ __align__(16) float dyn[];
    float* sA[2] = { dyn, dyn + AS_BYTES / 4 };
    float* sB[2] = { dyn + 2 * AS_BYTES / 4, dyn + 2 * AS_BYTES / 4 + BS_BYTES / 4 };

    const int tid = threadIdx.x;
    const int wid = tid >> 5;
    const int lane = tid & 31;
    const int gid = lane >> 2;   // 0..7
    const int tig = lane & 3;    // 0..3
    const int m0 = blockIdx.x * 128;
    const int n0 = blockIdx.y * 128;
    const int warpM = (wid >> 1) * 64;
    const int warpN = (wid & 1) * 64;

    const int nChunks = (K + 31) / 32;

    auto stage = [&](int chunk, int b) {
        const int k0 = chunk * 32;
        uint32_t sAu = smem_u32(sA[b]);
        uint32_t sBu = smem_u32(sB[b]);
#pragma unroll
        for (int it = 0; it < 8; it++) {
            int idx = tid + it * 128;
            int row = idx >> 3;
            int kq = (idx & 7) * 4;
            bool ok = (m0 + row < M) && (k0 + kq < K);
            const float* src = ok ? &A[(size_t)(m0 + row) * K + k0 + kq] : A;
            cp16(sAu + (row * AS_STRIDE + kq) * 4, src, ok ? 16 : 0);
        }
#pragma unroll
        for (int it = 0; it < 8; it++) {
            int idx = tid + it * 128;
            int k = idx >> 5;
            int nq = (idx & 31) * 4;
            bool ok = (k0 + k < K);
            const float* src = ok ? &B[(size_t)(k0 + k) * Ncols + n0 + nq] : B;
            cp16(sBu + (k * BS_STRIDE + nq) * 4, src, ok ? 16 : 0);
        }
        cp_commit();
    };

    float acc[4][8][4];
#pragma unroll
    for (int i = 0; i < 4; i++)
#pragma unroll
        for (int j = 0; j < 8; j++)
#pragma unroll
            for (int q = 0; q < 4; q++) acc[i][j][q] = 0.f;

    stage(0, 0);

    for (int t = 0; t < nChunks; t++) {
        if (t + 1 < nChunks) { stage(t + 1, (t + 1) & 1); cp_wait<1>(); }
        else                 { cp_wait<0>(); }
        __syncthreads();

        const float* cA = sA[t & 1];
        const float* cB = sB[t & 1];
#pragma unroll
        for (int kk = 0; kk < 32; kk += 8) {
            uint32_t af[4][4];
#pragma unroll
            for (int i = 0; i < 4; i++) {
                int r = warpM + i * 16 + gid;
                af[i][0] = f2tf32(cA[(r)     * AS_STRIDE + kk + tig]);
                af[i][1] = f2tf32(cA[(r + 8) * AS_STRIDE + kk + tig]);
                af[i][2] = f2tf32(cA[(r)     * AS_STRIDE + kk + tig + 4]);
                af[i][3] = f2tf32(cA[(r + 8) * AS_STRIDE + kk + tig + 4]);
            }
            uint32_t bf[8][2];
#pragma unroll
            for (int j = 0; j < 8; j++) {
                int n = warpN + j * 8 + gid;
                bf[j][0] = f2tf32(cB[(kk + tig)     * BS_STRIDE + n]);
                bf[j][1] = f2tf32(cB[(kk + tig + 4) * BS_STRIDE + n]);
            }
#pragma unroll
            for (int i = 0; i < 4; i++)
#pragma unroll
                for (int j = 0; j < 8; j++)
                    mma_tf32(acc[i][j][0], acc[i][j][1], acc[i][j][2], acc[i][j][3],
                             af[i][0], af[i][1], af[i][2], af[i][3],
                             bf[j][0], bf[j][1]);
        }
        __syncthreads();
    }

    // epilogue: head-major store.  col -> (h, c); col even & Cdim even, so
    // the float2 (col, col+1) never crosses a head boundary.
    int hj[8], cj[8];
    float bj0[8], bj1[8];
#pragma unroll
    for (int j = 0; j < 8; j++) {
        int col = n0 + warpN + j * 8 + tig * 2;
        int h = col / Cdim;
        hj[j] = h;
        cj[j] = col - h * Cdim;
        bj0[j] = __ldg(&bias[col]);
        bj1[j] = __ldg(&bias[col + 1]);
    }
#pragma unroll
    for (int i = 0; i < 4; i++) {
        int r0 = m0 + warpM + i * 16 + gid;
#pragma unroll
        for (int j = 0; j < 8; j++) {
            float* base = &Cmat[((size_t)hj[j] * M) * Cdim + cj[j]];
            if (r0 < M) {
                float2 v = make_float2(acc[i][j][0] + bj0[j], acc[i][j][1] + bj1[j]);
                *reinterpret_cast<float2*>(&base[(size_t)r0 * Cdim]) = v;
            }
            if (r0 + 8 < M) {
                float2 v = make_float2(acc[i][j][2] + bj0[j], acc[i][j][3] + bj1[j]);
                *reinterpret_cast<float2*>(&base[(size_t)(r0 + 8) * Cdim]) = v;
            }
        }
    }
}

// ---------------------------------------------------------------------------
// CSR construction
// ---------------------------------------------------------------------------
__global__ void init_deg_k(int* deg, int n) {
    int i = blockIdx.x * blockDim.x + threadIdx.x;
    if (i < n) deg[i] = 1;
}
__global__ void count_deg_k(const int* __restrict__ ei, int* deg, int E) {
    int e = blockIdx.x * blockDim.x + threadIdx.x;
    if (e < E) atomicAdd(&deg[ei[E + e]], 1);
}
__global__ void scan_rowptr_k(const int* __restrict__ deg, int* rowptr, int n) {
    __shared__ int sm[1024];
    __shared__ int carry;
    int tid = threadIdx.x;
    if (tid == 0) { carry = 0; rowptr[0] = 0; }
    __syncthreads();
    for (int base = 0; base < n; base += 1024) {
        int i = base + tid;
        int v = (i < n) ? deg[i] : 0;
        sm[tid] = v;
        __syncthreads();
        for (int off = 1; off < 1024; off <<= 1) {
            int t = (tid >= off) ? sm[tid - off] : 0;
            __syncthreads();
            sm[tid] += t;
            __syncthreads();
        }
        if (i < n) rowptr[i + 1] = carry + sm[tid];
        __syncthreads();
        if (tid == 0) carry += sm[1023];
        __syncthreads();
    }
}
__global__ void copy_cursor_k(const int* __restrict__ rowptr, int* cursor, int n) {
    int i = blockIdx.x * blockDim.x + threadIdx.x;
    if (i < n) cursor[i] = rowptr[i];
}
__global__ void scatter_edges_k(const int* __restrict__ ei, int* cursor,
                                int* colv, int E) {
    int e = blockIdx.x * blockDim.x + threadIdx.x;
    if (e < E) {
        int s = ei[e];
        int d = ei[E + e];
        int pos = atomicAdd(&cursor[d], 1);
        colv[pos] = s;
    }
}
__global__ void scatter_loops_k(int* cursor, int* colv, int n) {
    int i = blockIdx.x * blockDim.x + threadIdx.x;
    if (i < n) {
        int pos = atomicAdd(&cursor[i], 1);
        colv[pos] = i;
    }
}

// ---------------------------------------------------------------------------
// Edge attention, ALL heads per block.  Block = dst node, 128 threads.
// xl/xr are head-major: [h][Nn][C].  Head-mean kept in registers -> single
// non-atomic store; bias + optional leaky_relu fused.
// ---------------------------------------------------------------------------
template <int NCH>
__global__ __launch_bounds__(128) void gat_edge_k(
    const float* __restrict__ xl, const float* __restrict__ xr,
    const float* __restrict__ att, const int* __restrict__ rowptr,
    const int* __restrict__ colv, const float* __restrict__ bias,
    float* __restrict__ out,
    int C, int H, int Nn, float invH, float slope, int do_act)
{
    const int TPB = 128;
    int dst = blockIdx.x;
    int tid = threadIdx.x;
    __shared__ float ws[2][4];
    __shared__ int s_col[512];

    int e0 = rowptr[dst], e1 = rowptr[dst + 1];
    int deg = e1 - e0;
    for (int e = tid; e < deg && e < 512; e += TPB) s_col[e] = colv[e0 + e];
    __syncthreads();

    float macc[NCH];
#pragma unroll
    for (int j = 0; j < NCH; j++) macc[j] = 0.f;

    int ep = 0;   // parity counter, continuous across heads
    for (int h = 0; h < H; h++) {
        const float* xlh = xl + (size_t)h * Nn * C;
        const float* xrh = xr + (size_t)h * Nn * C;
        float a[NCH], xd[NCH], acc[NCH];
#pragma unroll
        for (int j = 0; j < NCH; j++) {
            int c = tid + j * TPB;
            bool ok = (NCH * TPB == C) || (c < C);
            a[j]   = ok ? att[h * C + c] : 0.f;
            xd[j]  = ok ? xrh[(size_t)dst * C + c] : 0.f;
            acc[j] = 0.f;
        }

        float m = -3.4e38f, l = 0.f;
        for (int e = 0; e < deg; e++, ep++) {
            int s = (e < 512) ? s_col[e] : colv[e0 + e];
            const float* xsp = xlh + (size_t)s * C;
            float xs[NCH];
            float p = 0.f;
#pragma unroll
            for (int j = 0; j < NCH; j++) {
                int c = tid + j * TPB;
                float xv = ((NCH * TPB == C) || c < C) ? xsp[c] : 0.f;
                xs[j] = xv;
                float v = xv + xd[j];
                v = v > 0.f ? v : 0.2f * v;
                p += a[j] * v;
            }
#pragma unroll
            for (int o = 16; o > 0; o >>= 1) p += __shfl_xor_sync(0xffffffffu, p, o);
            int slot = ep & 1;
            if ((tid & 31) == 0) ws[slot][tid >> 5] = p;
            __syncthreads();
            float ev = ws[slot][0] + ws[slot][1] + ws[slot][2] + ws[slot][3];

            float mn = fmaxf(m, ev);
            float sc = __expf(m - mn);
            float w  = __expf(ev - mn);
#pragma unroll
            for (int j = 0; j < NCH; j++) acc[j] = acc[j] * sc + w * xs[j];
            l = l * sc + w;
            m = mn;
        }

        float s = invH / l;
#pragma unroll
        for (int j = 0; j < NCH; j++) macc[j] += acc[j] * s;
    }

#pragma unroll
    for (int j = 0; j < NCH; j++) {
        int c = tid + j * TPB;
        if ((NCH * TPB == C) || c < C) {
            float v = macc[j] + bias[c];
            if (do_act) v = v > 0.f ? v : slope * v;
            out[(size_t)dst * C + c] = v;
        }
    }
}

// ---------------------------------------------------------------------------
// host orchestration
// ---------------------------------------------------------------------------
static void run_gemm(const float* A, const float* B, const float* bias, float* C,
                     int M, int K, int Ncols, int Cdim) {
    dim3 grid((M + 127) / 128, Ncols / 128);
    gemm_mma_k<<<grid, 128, GEMM_SMEM>>>(A, B, bias, C, M, K, Ncols, Cdim);
}

static void run_layer(const float* hin, int fi, int fo,
                      const float* Wl, const float* bl,
                      const float* Wr, const float* br,
                      const float* att, const float* bias,
                      float* xl, float* xr,
                      const int* rowptr, const int* colv,
                      float* hout, int N, int H, bool act) {
    int Ncols = H * fo;
    run_gemm(hin, Wl, bl, xl, N, fi, Ncols, fo);
    run_gemm(hin, Wr, br, xr, N, fi, Ncols, fo);

    float invH = 1.f / (float)H;
    if (fo == 128)
        gat_edge_k<1><<<N, 128>>>(xl, xr, att, rowptr, colv, bias, hout,
                                  fo, H, N, invH, 0.01f, act ? 1 : 0);
    else if (fo == 512)
        gat_edge_k<4><<<N, 128>>>(xl, xr, att, rowptr, colv, bias, hout,
                                  fo, H, N, invH, 0.01f, act ? 1 : 0);
    else
        gat_edge_k<9><<<N, 128>>>(xl, xr, att, rowptr, colv, bias, hout,
                                  fo, H, N, invH, 0.01f, act ? 1 : 0);
}

extern "C" void kernel_launch(void* const* d_in, const int* in_sizes, int n_in,
                              void* d_out, int out_size) {
    const float* x  = (const float*)d_in[0];
    const int*   ei = (const int*)d_in[1];

    const float* W1l = (const float*)d_in[2];
    const float* b1l = (const float*)d_in[3];
    const float* W1r = (const float*)d_in[4];
    const float* b1r = (const float*)d_in[5];
    const float* at1 = (const float*)d_in[6];
    const float* bi1 = (const float*)d_in[7];
    const float* W2l = (const float*)d_in[8];
    const float* b2l = (const float*)d_in[9];
    const float* W2r = (const float*)d_in[10];
    const float* b2r = (const float*)d_in[11];
    const float* at2 = (const float*)d_in[12];
    const float* bi2 = (const float*)d_in[13];
    const float* W3l = (const float*)d_in[14];
    const float* b3l = (const float*)d_in[15];
    const float* W3r = (const float*)d_in[16];
    const float* b3r = (const float*)d_in[17];
    const float* at3 = (const float*)d_in[18];
    const float* bi3 = (const float*)d_in[19];

    int N = in_sizes[0] / 4;
    int E = in_sizes[1] / 2;
    int f1 = in_sizes[7];
    int f2 = in_sizes[13];
    int f3 = in_sizes[19];
    int H  = in_sizes[3] / f1;

    cudaFuncSetAttribute(gemm_mma_k, cudaFuncAttributeMaxDynamicSharedMemorySize,
                         GEMM_SMEM);

    float *xl, *xr, *h1, *h2;
    int *deg, *rowptr, *cursor, *colv;
    cudaGetSymbolAddress((void**)&xl, g_xl);
    cudaGetSymbolAddress((void**)&xr, g_xr);
    cudaGetSymbolAddress((void**)&h1, g_h1);
    cudaGetSymbolAddress((void**)&h2, g_h2);
    cudaGetSymbolAddress((void**)&deg, g_deg);
    cudaGetSymbolAddress((void**)&rowptr, g_rowptr);
    cudaGetSymbolAddress((void**)&cursor, g_cursor);
    cudaGetSymbolAddress((void**)&colv, g_col);

    // --- CSR build (by destination) ---
    init_deg_k<<<(N + 255) / 256, 256>>>(deg, N);
    count_deg_k<<<(E + 255) / 256, 256>>>(ei, deg, E);
    scan_rowptr_k<<<1, 1024>>>(deg, rowptr, N);
    copy_cursor_k<<<(N + 255) / 256, 256>>>(rowptr, cursor, N);
    scatter_edges_k<<<(E + 255) / 256, 256>>>(ei, cursor, colv, E);
    scatter_loops_k<<<(N + 255) / 256, 256>>>(cursor, colv, N);

    // --- 3 GATv2 layers ---
    run_layer(x,  4,  f1, W1l, b1l, W1r, b1r, at1, bi1, xl, xr, rowptr, colv, h1, N, H, true);
    run_layer(h1, f1, f2, W2l, b2l, W2r, b2r, at2, bi2, xl, xr, rowptr, colv, h2, N, H, true);
    run_layer(h2, f2, f3, W3l, b3l, W3r, b3r, at3, bi3, xl, xr, rowptr, colv,
              (float*)d_out, N, H, false);
}

// round 6
// speedup vs baseline: 1.2716x; 1.2716x over previous
#include <cuda_runtime.h>
#include <cstdint>
#include <cstddef>

// ---------------------------------------------------------------------------
// GATv2 x3 layers.  Dims: 4 -> 128 -> 512 -> 1028, H=32 heads, head-mean.
//   GEMMs: mma.sync.m16n8k8 tf32, 128x128 CTA tile, 4 warps x (64x64),
//     BK=32, cp.async double buffer.  Inputs PRE-ROUNDED to tf32 so the
//     mainloop has zero cvt instructions.  Epilogue writes HEAD-MAJOR
//     scratch xl/xr: [h][n][c].
//   Edge phase: block per (dst, head) (320k CTAs for latency hiding),
//     online softmax, per-head result to g_acc[h][n][c] (no atomics, no
//     zero-pass).  Mean over heads + bias + leaky + tf32-round fused in a
//     streaming epilogue kernel.
// ---------------------------------------------------------------------------

#define MAX_N 10000
#define MAX_E 160000
#define MAX_EL (MAX_E + MAX_N)

// scratch (allocation-free rule: __device__ globals)
__device__ float g_xl[328960000];          // 10000 * 32 * 1028
__device__ float g_xr[328960000];
__device__ float g_acc[328960000];
__device__ float g_wl[16842752];           // 512 * 32896 (max weight)
__device__ float g_wr[16842752];
__device__ float g_a0[40000];              // rounded x (N x 4)
__device__ float g_h1[MAX_N * 128];
__device__ float g_h2[MAX_N * 512];
__device__ int   g_deg[MAX_N];
__device__ int   g_rowptr[MAX_N + 1];
__device__ int   g_cursor[MAX_N];
__device__ int   g_col[MAX_EL];

// ---------------------------------------------------------------------------
// helpers
// ---------------------------------------------------------------------------
__device__ __forceinline__ void cp16(uint32_t dst, const void* src, int bytes) {
    asm volatile("cp.async.cg.shared.global [%0], [%1], 16, %2;"
                 :: "r"(dst), "l"(src), "r"(bytes) : "memory");
}
__device__ __forceinline__ void cp_commit() {
    asm volatile("cp.async.commit_group;" ::: "memory");
}
template <int N>
__device__ __forceinline__ void cp_wait() {
    asm volatile("cp.async.wait_group %0;" :: "n"(N) : "memory");
}
__device__ __forceinline__ uint32_t smem_u32(const void* p) {
    uint32_t a;
    asm("{ .reg .u64 t; cvta.to.shared.u64 t, %1; cvt.u32.u64 %0, t; }"
        : "=r"(a) : "l"(p));
    return a;
}
__device__ __forceinline__ float f2tf32f(float x) {
    uint32_t u;
    asm("cvt.rna.tf32.f32 %0, %1;" : "=r"(u) : "f"(x));
    return __uint_as_float(u);
}
__device__ __forceinline__ void mma_tf32(float& c0, float& c1, float& c2, float& c3,
                                         uint32_t a0, uint32_t a1, uint32_t a2, uint32_t a3,
                                         uint32_t b0, uint32_t b1) {
    asm volatile(
        "mma.sync.aligned.m16n8k8.row.col.f32.tf32.tf32.f32 "
        "{%0,%1,%2,%3}, {%4,%5,%6,%7}, {%8,%9}, {%0,%1,%2,%3};"
        : "+f"(c0), "+f"(c1), "+f"(c2), "+f"(c3)
        : "r"(a0), "r"(a1), "r"(a2), "r"(a3), "r"(b0), "r"(b1));
}

// elementwise tf32 rounding (for weights / input x)
__global__ void round_tf32_k(const float* __restrict__ in, float* __restrict__ out,
                             int n) {
    int i = blockIdx.x * blockDim.x + threadIdx.x;
    if (i < n) out[i] = f2tf32f(in[i]);
}

// ---------------------------------------------------------------------------
// mma.sync tf32 GEMM, inputs assumed already tf32-rounded.
// C_out[h][m][c] = (A[M,K] @ B[K,H*C])[m, h*C+c] + bias[h*C+c]   (head-major)
// ---------------------------------------------------------------------------
#define AS_STRIDE 36
#define BS_STRIDE 136
#define AS_BYTES (128 * AS_STRIDE * 4)   // 18432
#define BS_BYTES (32 * BS_STRIDE * 4)    // 17408
#define GEMM_SMEM (2 * (AS_BYTES + BS_BYTES))  // 71680

__global__ __launch_bounds__(128, 2) void gemm_mma_k(
    const float* __restrict__ A, const float* __restrict__ B,
    const float* __restrict__ bias, float* __restrict__ Cmat,
    int M, int K, int Ncols, int Cdim)
{
    extern __shared__ __align__(16) float dyn[];
    float* sA[2] = { dyn, dyn + AS_BYTES / 4 };
    float* sB[2] = { dyn + 2 * AS_BYTES / 4, dyn + 2 * AS_BYTES / 4 + BS_BYTES / 4 };

    const int tid = threadIdx.x;
    const int wid = tid >> 5;
    const int lane = tid & 31;
    const int gid = lane >> 2;
    const int tig = lane & 3;
    const int m0 = blockIdx.x * 128;
    const int n0 = blockIdx.y * 128;
    const int warpM = (wid >> 1) * 64;
    const int warpN = (wid & 1) * 64;

    const int nChunks = (K + 31) / 32;

    auto stage = [&](int chunk, int b) {
        const int k0 = chunk * 32;
        uint32_t sAu = smem_u32(sA[b]);
        uint32_t sBu = smem_u32(sB[b]);
#pragma unroll
        for (int it = 0; it < 8; it++) {
            int idx = tid + it * 128;
            int row = idx >> 3;
            int kq = (idx & 7) * 4;
            bool ok = (m0 + row < M) && (k0 + kq < K);
            const float* src = ok ? &A[(size_t)(m0 + row) * K + k0 + kq] : A;
            cp16(sAu + (row * AS_STRIDE + kq) * 4, src, ok ? 16 : 0);
        }
#pragma unroll
        for (int it = 0; it < 8; it++) {
            int idx = tid + it * 128;
            int k = idx >> 5;
            int nq = (idx & 31) * 4;
            bool ok = (k0 + k < K);
            const float* src = ok ? &B[(size_t)(k0 + k) * Ncols + n0 + nq] : B;
            cp16(sBu + (k * BS_STRIDE + nq) * 4, src, ok ? 16 : 0);
        }
        cp_commit();
    };

    float acc[4][8][4];
#pragma unroll
    for (int i = 0; i < 4; i++)
#pragma unroll
        for (int j = 0; j < 8; j++)
#pragma unroll
            for (int q = 0; q < 4; q++) acc[i][j][q] = 0.f;

    stage(0, 0);

    for (int t = 0; t < nChunks; t++) {
        if (t + 1 < nChunks) { stage(t + 1, (t + 1) & 1); cp_wait<1>(); }
        else                 { cp_wait<0>(); }
        __syncthreads();

        const float* cA = sA[t & 1];
        const float* cB = sB[t & 1];
#pragma unroll
        for (int kk = 0; kk < 32; kk += 8) {
            uint32_t af[4][4];
#pragma unroll
            for (int i = 0; i < 4; i++) {
                int r = warpM + i * 16 + gid;
                af[i][0] = __float_as_uint(cA[(r)     * AS_STRIDE + kk + tig]);
                af[i][1] = __float_as_uint(cA[(r + 8) * AS_STRIDE + kk + tig]);
                af[i][2] = __float_as_uint(cA[(r)     * AS_STRIDE + kk + tig + 4]);
                af[i][3] = __float_as_uint(cA[(r + 8) * AS_STRIDE + kk + tig + 4]);
            }
            uint32_t bf[8][2];
#pragma unroll
            for (int j = 0; j < 8; j++) {
                int n = warpN + j * 8 + gid;
                bf[j][0] = __float_as_uint(cB[(kk + tig)     * BS_STRIDE + n]);
                bf[j][1] = __float_as_uint(cB[(kk + tig + 4) * BS_STRIDE + n]);
            }
#pragma unroll
            for (int i = 0; i < 4; i++)
#pragma unroll
                for (int j = 0; j < 8; j++)
                    mma_tf32(acc[i][j][0], acc[i][j][1], acc[i][j][2], acc[i][j][3],
                             af[i][0], af[i][1], af[i][2], af[i][3],
                             bf[j][0], bf[j][1]);
        }
        __syncthreads();
    }

    // epilogue: head-major store (col even, Cdim even -> float2 stays in head)
    int hj[8], cj[8];
    float bj0[8], bj1[8];
#pragma unroll
    for (int j = 0; j < 8; j++) {
        int col = n0 + warpN + j * 8 + tig * 2;
        int h = col / Cdim;
        hj[j] = h;
        cj[j] = col - h * Cdim;
        bj0[j] = __ldg(&bias[col]);
        bj1[j] = __ldg(&bias[col + 1]);
    }
#pragma unroll
    for (int i = 0; i < 4; i++) {
        int r0 = m0 + warpM + i * 16 + gid;
#pragma unroll
        for (int j = 0; j < 8; j++) {
            float* base = &Cmat[((size_t)hj[j] * M) * Cdim + cj[j]];
            if (r0 < M) {
                float2 v = make_float2(acc[i][j][0] + bj0[j], acc[i][j][1] + bj1[j]);
                *reinterpret_cast<float2*>(&base[(size_t)r0 * Cdim]) = v;
            }
            if (r0 + 8 < M) {
                float2 v = make_float2(acc[i][j][2] + bj0[j], acc[i][j][3] + bj1[j]);
                *reinterpret_cast<float2*>(&base[(size_t)(r0 + 8) * Cdim]) = v;
            }
        }
    }
}

// ---------------------------------------------------------------------------
// CSR construction
// ---------------------------------------------------------------------------
__global__ void init_deg_k(int* deg, int n) {
    int i = blockIdx.x * blockDim.x + threadIdx.x;
    if (i < n) deg[i] = 1;
}
__global__ void count_deg_k(const int* __restrict__ ei, int* deg, int E) {
    int e = blockIdx.x * blockDim.x + threadIdx.x;
    if (e < E) atomicAdd(&deg[ei[E + e]], 1);
}
__global__ void scan_rowptr_k(const int* __restrict__ deg, int* rowptr, int n) {
    __shared__ int sm[1024];
    __shared__ int carry;
    int tid = threadIdx.x;
    if (tid == 0) { carry = 0; rowptr[0] = 0; }
    __syncthreads();
    for (int base = 0; base < n; base += 1024) {
        int i = base + tid;
        int v = (i < n) ? deg[i] : 0;
        sm[tid] = v;
        __syncthreads();
        for (int off = 1; off < 1024; off <<= 1) {
            int t = (tid >= off) ? sm[tid - off] : 0;
            __syncthreads();
            sm[tid] += t;
            __syncthreads();
        }
        if (i < n) rowptr[i + 1] = carry + sm[tid];
        __syncthreads();
        if (tid == 0) carry += sm[1023];
        __syncthreads();
    }
}
__global__ void copy_cursor_k(const int* __restrict__ rowptr, int* cursor, int n) {
    int i = blockIdx.x * blockDim.x + threadIdx.x;
    if (i < n) cursor[i] = rowptr[i];
}
__global__ void scatter_edges_k(const int* __restrict__ ei, int* cursor,
                                int* colv, int E) {
    int e = blockIdx.x * blockDim.x + threadIdx.x;
    if (e < E) {
        int s = ei[e];
        int d = ei[E + e];
        int pos = atomicAdd(&cursor[d], 1);
        colv[pos] = s;
    }
}
__global__ void scatter_loops_k(int* cursor, int* colv, int n) {
    int i = blockIdx.x * blockDim.x + threadIdx.x;
    if (i < n) {
        int pos = atomicAdd(&cursor[i], 1);
        colv[pos] = i;
    }
}

// ---------------------------------------------------------------------------
// Edge attention.  Block = (dst, head), 128 threads.  Head-major xl/xr.
// Writes per-head alpha-weighted sum (divided by l) into acc[h][n][c].
// ---------------------------------------------------------------------------
template <int NCH>
__global__ __launch_bounds__(128) void gat_edge_k(
    const float* __restrict__ xl, const float* __restrict__ xr,
    const float* __restrict__ att, const int* __restrict__ rowptr,
    const int* __restrict__ colv, float* __restrict__ accm,
    int C, int Nn)
{
    const int TPB = 128;
    int dst = blockIdx.x;
    int h = blockIdx.y;
    int tid = threadIdx.x;
    __shared__ float ws[2][4];

    const float* xlh = xl + (size_t)h * Nn * C;
    const float* xrh = xr + (size_t)h * Nn * C;

    float a[NCH], xd[NCH], acc[NCH];
#pragma unroll
    for (int j = 0; j < NCH; j++) {
        int c = tid + j * TPB;
        bool ok = (NCH * TPB == C) || (c < C);
        a[j]   = ok ? att[h * C + c] : 0.f;
        xd[j]  = ok ? xrh[(size_t)dst * C + c] : 0.f;
        acc[j] = 0.f;
    }

    float m = -3.4e38f, l = 0.f;
    int e0 = rowptr[dst], e1 = rowptr[dst + 1];
    for (int e = e0; e < e1; e++) {
        int s = __ldg(&colv[e]);
        const float* xsp = xlh + (size_t)s * C;
        float xs[NCH];
        float p = 0.f;
#pragma unroll
        for (int j = 0; j < NCH; j++) {
            int c = tid + j * TPB;
            float xv = ((NCH * TPB == C) || c < C) ? xsp[c] : 0.f;
            xs[j] = xv;
            float v = xv + xd[j];
            v = v > 0.f ? v : 0.2f * v;
            p += a[j] * v;
        }
#pragma unroll
        for (int o = 16; o > 0; o >>= 1) p += __shfl_xor_sync(0xffffffffu, p, o);
        int slot = e & 1;
        if ((tid & 31) == 0) ws[slot][tid >> 5] = p;
        __syncthreads();
        float ev = ws[slot][0] + ws[slot][1] + ws[slot][2] + ws[slot][3];

        float mn = fmaxf(m, ev);
        float sc = __expf(m - mn);
        float w  = __expf(ev - mn);
#pragma unroll
        for (int j = 0; j < NCH; j++) acc[j] = acc[j] * sc + w * xs[j];
        l = l * sc + w;
        m = mn;
    }

    float inv = 1.f / l;
    float* dstp = accm + ((size_t)h * Nn + dst) * C;
#pragma unroll
    for (int j = 0; j < NCH; j++) {
        int c = tid + j * TPB;
        if ((NCH * TPB == C) || c < C) dstp[c] = acc[j] * inv;
    }
}

// ---------------------------------------------------------------------------
// Head mean + bias + optional leaky + optional tf32 rounding (streaming)
// ---------------------------------------------------------------------------
__global__ void mean_bias_act_k(const float* __restrict__ accm,
                                const float* __restrict__ bias,
                                float* __restrict__ out,
                                int total, int C, size_t sliceN, int H,
                                float invH, float slope, int do_act, int do_round) {
    int i = blockIdx.x * blockDim.x + threadIdx.x;
    if (i >= total) return;
    float s = 0.f;
    for (int h = 0; h < H; h++) s += accm[(size_t)h * sliceN + i];
    float v = s * invH + bias[i % C];
    if (do_act) v = v > 0.f ? v : slope * v;
    if (do_round) v = f2tf32f(v);
    out[i] = v;
}

// ---------------------------------------------------------------------------
// host orchestration
// ---------------------------------------------------------------------------
static void run_gemm(const float* A, const float* B, const float* bias, float* C,
                     int M, int K, int Ncols, int Cdim) {
    dim3 grid((M + 127) / 128, Ncols / 128);
    gemm_mma_k<<<grid, 128, GEMM_SMEM>>>(A, B, bias, C, M, K, Ncols, Cdim);
}

static void run_layer(const float* hin, int fi, int fo,
                      const float* Wl, const float* bl,
                      const float* Wr, const float* br,
                      const float* att, const float* bias,
                      float* xl, float* xr, float* accm, float* wl, float* wr,
                      const int* rowptr, const int* colv,
                      float* hout, int N, int H, bool act, bool roundOut) {
    int Ncols = H * fo;
    int wN = fi * Ncols;
    round_tf32_k<<<(wN + 255) / 256, 256>>>(Wl, wl, wN);
    round_tf32_k<<<(wN + 255) / 256, 256>>>(Wr, wr, wN);
    run_gemm(hin, wl, bl, xl, N, fi, Ncols, fo);
    run_gemm(hin, wr, br, xr, N, fi, Ncols, fo);

    dim3 eg(N, H);
    if (fo == 128)
        gat_edge_k<1><<<eg, 128>>>(xl, xr, att, rowptr, colv, accm, fo, N);
    else if (fo == 512)
        gat_edge_k<4><<<eg, 128>>>(xl, xr, att, rowptr, colv, accm, fo, N);
    else
        gat_edge_k<9><<<eg, 128>>>(xl, xr, att, rowptr, colv, accm, fo, N);

    int total = N * fo;
    mean_bias_act_k<<<(total + 255) / 256, 256>>>(
        accm, bias, hout, total, fo, (size_t)N * fo, H,
        1.f / (float)H, 0.01f, act ? 1 : 0, roundOut ? 1 : 0);
}

extern "C" void kernel_launch(void* const* d_in, const int* in_sizes, int n_in,
                              void* d_out, int out_size) {
    const float* x  = (const float*)d_in[0];
    const int*   ei = (const int*)d_in[1];

    const float* W1l = (const float*)d_in[2];
    const float* b1l = (const float*)d_in[3];
    const float* W1r = (const float*)d_in[4];
    const float* b1r = (const float*)d_in[5];
    const float* at1 = (const float*)d_in[6];
    const float* bi1 = (const float*)d_in[7];
    const float* W2l = (const float*)d_in[8];
    const float* b2l = (const float*)d_in[9];
    const float* W2r = (const float*)d_in[10];
    const float* b2r = (const float*)d_in[11];
    const float* at2 = (const float*)d_in[12];
    const float* bi2 = (const float*)d_in[13];
    const float* W3l = (const float*)d_in[14];
    const float* b3l = (const float*)d_in[15];
    const float* W3r = (const float*)d_in[16];
    const float* b3r = (const float*)d_in[17];
    const float* at3 = (const float*)d_in[18];
    const float* bi3 = (const float*)d_in[19];

    int N = in_sizes[0] / 4;
    int E = in_sizes[1] / 2;
    int f1 = in_sizes[7];
    int f2 = in_sizes[13];
    int f3 = in_sizes[19];
    int H  = in_sizes[3] / f1;

    cudaFuncSetAttribute(gemm_mma_k, cudaFuncAttributeMaxDynamicSharedMemorySize,
                         GEMM_SMEM);

    float *xl, *xr, *accm, *wl, *wr, *a0, *h1, *h2;
    int *deg, *rowptr, *cursor, *colv;
    cudaGetSymbolAddress((void**)&xl, g_xl);
    cudaGetSymbolAddress((void**)&xr, g_xr);
    cudaGetSymbolAddress((void**)&accm, g_acc);
    cudaGetSymbolAddress((void**)&wl, g_wl);
    cudaGetSymbolAddress((void**)&wr, g_wr);
    cudaGetSymbolAddress((void**)&a0, g_a0);
    cudaGetSymbolAddress((void**)&h1, g_h1);
    cudaGetSymbolAddress((void**)&h2, g_h2);
    cudaGetSymbolAddress((void**)&deg, g_deg);
    cudaGetSymbolAddress((void**)&rowptr, g_rowptr);
    cudaGetSymbolAddress((void**)&cursor, g_cursor);
    cudaGetSymbolAddress((void**)&colv, g_col);

    // --- CSR build (by destination) ---
    init_deg_k<<<(N + 255) / 256, 256>>>(deg, N);
    count_deg_k<<<(E + 255) / 256, 256>>>(ei, deg, E);
    scan_rowptr_k<<<1, 1024>>>(deg, rowptr, N);
    copy_cursor_k<<<(N + 255) / 256, 256>>>(rowptr, cursor, N);
    scatter_edges_k<<<(E + 255) / 256, 256>>>(ei, cursor, colv, E);
    scatter_loops_k<<<(N + 255) / 256, 256>>>(cursor, colv, N);

    // --- pre-round input x ---
    round_tf32_k<<<(N * 4 + 255) / 256, 256>>>(x, a0, N * 4);

    // --- 3 GATv2 layers ---
    run_layer(a0, 4,  f1, W1l, b1l, W1r, b1r, at1, bi1,
              xl, xr, accm, wl, wr, rowptr, colv, h1, N, H, true, true);
    run_layer(h1, f1, f2, W2l, b2l, W2r, b2r, at2, bi2,
              xl, xr, accm, wl, wr, rowptr, colv, h2, N, H, true, true);
    run_layer(h2, f2, f3, W3l, b3l, W3r, b3r, at3, bi3,
              xl, xr, accm, wl, wr, rowptr, colv, (float*)d_out, N, H, false, false);
}

// round 7
// speedup vs baseline: 1.4695x; 1.1557x over previous
#include <cuda_runtime.h>
#include <cuda_fp16.h>
#include <cstdint>
#include <cstddef>

// ---------------------------------------------------------------------------
// GATv2 x3 layers.  Dims: 4 -> 128 -> 512 -> 1028, H=32 heads, head-mean.
//   GEMMs: mma.sync.m16n8k16 fp16 (fp32 accum), 128x128 CTA tile,
//     4 warps x (64x64), BK=32, cp.async double buffer.  A (activations) and
//     B (weights, pre-transposed [n][k]) stored fp16 in global.
//   Edge phase: block per (dst, head), online softmax, fp32 head-major
//     scratch, no atomics.  Mean+bias+act epilogue emits fp16 for next layer.
// ---------------------------------------------------------------------------

#define MAX_N 10000
#define MAX_E 160000
#define MAX_EL (MAX_E + MAX_N)

// scratch (allocation-free rule: __device__ globals)
__device__ float  g_xl[328960000];          // 10000 * 32 * 1028
__device__ float  g_xr[328960000];
__device__ float  g_acc[328960000];
__device__ __half g_wlh[16842752];          // transposed half weights (max 32896x512)
__device__ __half g_wrh[16842752];
__device__ __half g_a0h[80000];             // x as half, padded K=8
__device__ __half g_h1h[1280000];           // N x 128
__device__ __half g_h2h[5120000];           // N x 512
__device__ int    g_deg[MAX_N];
__device__ int    g_rowptr[MAX_N + 1];
__device__ int    g_cursor[MAX_N];
__device__ int    g_col[MAX_EL];

// ---------------------------------------------------------------------------
// helpers
// ---------------------------------------------------------------------------
__device__ __forceinline__ void cp16(uint32_t dst, const void* src, int bytes) {
    asm volatile("cp.async.cg.shared.global [%0], [%1], 16, %2;"
                 :: "r"(dst), "l"(src), "r"(bytes) : "memory");
}
__device__ __forceinline__ void cp_commit() {
    asm volatile("cp.async.commit_group;" ::: "memory");
}
template <int N>
__device__ __forceinline__ void cp_wait() {
    asm volatile("cp.async.wait_group %0;" :: "n"(N) : "memory");
}
__device__ __forceinline__ uint32_t smem_u32(const void* p) {
    uint32_t a;
    asm("{ .reg .u64 t; cvta.to.shared.u64 t, %1; cvt.u32.u64 %0, t; }"
        : "=r"(a) : "l"(p));
    return a;
}
__device__ __forceinline__ void mma_fp16(float& c0, float& c1, float& c2, float& c3,
                                         uint32_t a0, uint32_t a1, uint32_t a2, uint32_t a3,
                                         uint32_t b0, uint32_t b1) {
    asm volatile(
        "mma.sync.aligned.m16n8k16.row.col.f32.f16.f16.f32 "
        "{%0,%1,%2,%3}, {%4,%5,%6,%7}, {%8,%9}, {%0,%1,%2,%3};"
        : "+f"(c0), "+f"(c1), "+f"(c2), "+f"(c3)
        : "r"(a0), "r"(a1), "r"(a2), "r"(a3), "r"(b0), "r"(b1));
}

// ---------------------------------------------------------------------------
// weight convert + transpose:  Wt[n][k] = (half)W[k][n],  row stride ldwt
// (zero-padded for k in [K, ldwt)).
// ---------------------------------------------------------------------------
__global__ void conv_trans_k(const float* __restrict__ W, __half* __restrict__ Wt,
                             int K, int Ncols, int ldwt) {
    __shared__ float t[32][33];
    int n0 = blockIdx.x * 32;
    int k0 = blockIdx.y * 32;
    int tx = threadIdx.x;   // 0..31
    int ty = threadIdx.y;   // 0..7
    for (int i = ty; i < 32; i += 8) {
        int k = k0 + i;
        int n = n0 + tx;
        t[i][tx] = (k < K && n < Ncols) ? W[(size_t)k * Ncols + n] : 0.f;
    }
    __syncthreads();
    for (int i = ty; i < 32; i += 8) {
        int n = n0 + i;
        int k = k0 + tx;
        if (n < Ncols && k < ldwt)
            Wt[(size_t)n * ldwt + k] = __float2half(t[tx][i]);
    }
}

// x -> half, padded to lda columns (zeros beyond K)
__global__ void conv_x_k(const float* __restrict__ x, __half* __restrict__ out,
                         int N, int K, int lda) {
    int i = blockIdx.x * blockDim.x + threadIdx.x;
    if (i < N * lda) {
        int row = i / lda, col = i - row * lda;
        out[i] = __float2half(col < K ? x[row * K + col] : 0.f);
    }
}

// ---------------------------------------------------------------------------
// fp16 GEMM:  C_out[h][m][c] = (A[M,K] @ Bt^T)[m, h*C+c] + bias   (head-major)
// A: half [M][lda], Bt: half [Ncols][ldb] (= W transposed).
// ---------------------------------------------------------------------------
#define AS 40                               // halfs per smem row
#define TILE_BYTES (128 * AS * 2)           // 10240
#define GEMM_SMEM (4 * TILE_BYTES)          // 40960

__global__ __launch_bounds__(128, 2) void gemm_h_k(
    const __half* __restrict__ A, const __half* __restrict__ Bt,
    const float* __restrict__ bias, float* __restrict__ Cmat,
    int M, int K, int lda, int ldb, int Ncols, int Cdim)
{
    extern __shared__ __align__(16) __half dyn[];
    __half* sA[2] = { dyn,                    dyn + TILE_BYTES / 2 };
    __half* sB[2] = { dyn + TILE_BYTES,       dyn + 3 * TILE_BYTES / 2 };

    const int tid = threadIdx.x;
    const int wid = tid >> 5;
    const int lane = tid & 31;
    const int gid = lane >> 2;   // 0..7
    const int tig = lane & 3;    // 0..3
    const int m0 = blockIdx.x * 128;
    const int n0 = blockIdx.y * 128;
    const int warpM = (wid >> 1) * 64;
    const int warpN = (wid & 1) * 64;

    const int nChunks = (K + 31) / 32;

    auto stage = [&](int chunk, int b) {
        const int k0 = chunk * 32;
        uint32_t sAu = smem_u32(sA[b]);
        uint32_t sBu = smem_u32(sB[b]);
#pragma unroll
        for (int it = 0; it < 4; it++) {            // A: 128 rows x 4 x 16B
            int idx = tid + it * 128;
            int row = idx >> 2;
            int seg = (idx & 3) * 8;                // half offset
            int gk = k0 + seg;
            int rem = (K - gk) * 2;
            int bytes = (m0 + row < M) ? (rem < 0 ? 0 : (rem > 16 ? 16 : rem)) : 0;
            const __half* src = bytes ? &A[(size_t)(m0 + row) * lda + gk] : A;
            cp16(sAu + (row * AS + seg) * 2, src, bytes);
        }
#pragma unroll
        for (int it = 0; it < 4; it++) {            // B: 128 rows x 4 x 16B
            int idx = tid + it * 128;
            int row = idx >> 2;
            int seg = (idx & 3) * 8;
            int gk = k0 + seg;
            int rem = (K - gk) * 2;
            int bytes = rem < 0 ? 0 : (rem > 16 ? 16 : rem);
            const __half* src = bytes ? &Bt[(size_t)(n0 + row) * ldb + gk] : Bt;
            cp16(sBu + (row * AS + seg) * 2, src, bytes);
        }
        cp_commit();
    };

    float acc[4][8][4];
#pragma unroll
    for (int i = 0; i < 4; i++)
#pragma unroll
        for (int j = 0; j < 8; j++)
#pragma unroll
            for (int q = 0; q < 4; q++) acc[i][j][q] = 0.f;

    stage(0, 0);

    for (int t = 0; t < nChunks; t++) {
        if (t + 1 < nChunks) { stage(t + 1, (t + 1) & 1); cp_wait<1>(); }
        else                 { cp_wait<0>(); }
        __syncthreads();

        const __half* cA = sA[t & 1];
        const __half* cB = sB[t & 1];
#pragma unroll
        for (int kk = 0; kk < 32; kk += 16) {
            uint32_t af[4][4];
#pragma unroll
            for (int i = 0; i < 4; i++) {
                int r = warpM + i * 16 + gid;
                af[i][0] = *(const uint32_t*)&cA[(r)     * AS + kk + 2 * tig];
                af[i][1] = *(const uint32_t*)&cA[(r + 8) * AS + kk + 2 * tig];
                af[i][2] = *(const uint32_t*)&cA[(r)     * AS + kk + 2 * tig + 8];
                af[i][3] = *(const uint32_t*)&cA[(r + 8) * AS + kk + 2 * tig + 8];
            }
            uint32_t bf[8][2];
#pragma unroll
            for (int j = 0; j < 8; j++) {
                int n = warpN + j * 8 + gid;
                bf[j][0] = *(const uint32_t*)&cB[n * AS + kk + 2 * tig];
                bf[j][1] = *(const uint32_t*)&cB[n * AS + kk + 2 * tig + 8];
            }
#pragma unroll
            for (int i = 0; i < 4; i++)
#pragma unroll
                for (int j = 0; j < 8; j++)
                    mma_fp16(acc[i][j][0], acc[i][j][1], acc[i][j][2], acc[i][j][3],
                             af[i][0], af[i][1], af[i][2], af[i][3],
                             bf[j][0], bf[j][1]);
        }
        __syncthreads();
    }

    // epilogue: head-major store (col even, Cdim even -> float2 stays in head)
    int hj[8], cj[8];
    float bj0[8], bj1[8];
#pragma unroll
    for (int j = 0; j < 8; j++) {
        int col = n0 + warpN + j * 8 + tig * 2;
        int h = col / Cdim;
        hj[j] = h;
        cj[j] = col - h * Cdim;
        bj0[j] = __ldg(&bias[col]);
        bj1[j] = __ldg(&bias[col + 1]);
    }
#pragma unroll
    for (int i = 0; i < 4; i++) {
        int r0 = m0 + warpM + i * 16 + gid;
#pragma unroll
        for (int j = 0; j < 8; j++) {
            float* base = &Cmat[((size_t)hj[j] * M) * Cdim + cj[j]];
            if (r0 < M) {
                float2 v = make_float2(acc[i][j][0] + bj0[j], acc[i][j][1] + bj1[j]);
                *reinterpret_cast<float2*>(&base[(size_t)r0 * Cdim]) = v;
            }
            if (r0 + 8 < M) {
                float2 v = make_float2(acc[i][j][2] + bj0[j], acc[i][j][3] + bj1[j]);
                *reinterpret_cast<float2*>(&base[(size_t)(r0 + 8) * Cdim]) = v;
            }
        }
    }
}

// ---------------------------------------------------------------------------
// CSR construction
// ---------------------------------------------------------------------------
__global__ void init_deg_k(int* deg, int n) {
    int i = blockIdx.x * blockDim.x + threadIdx.x;
    if (i < n) deg[i] = 1;
}
__global__ void count_deg_k(const int* __restrict__ ei, int* deg, int E) {
    int e = blockIdx.x * blockDim.x + threadIdx.x;
    if (e < E) atomicAdd(&deg[ei[E + e]], 1);
}
__global__ void scan_rowptr_k(const int* __restrict__ deg, int* rowptr, int n) {
    __shared__ int sm[1024];
    __shared__ int carry;
    int tid = threadIdx.x;
    if (tid == 0) { carry = 0; rowptr[0] = 0; }
    __syncthreads();
    for (int base = 0; base < n; base += 1024) {
        int i = base + tid;
        int v = (i < n) ? deg[i] : 0;
        sm[tid] = v;
        __syncthreads();
        for (int off = 1; off < 1024; off <<= 1) {
            int t = (tid >= off) ? sm[tid - off] : 0;
            __syncthreads();
            sm[tid] += t;
            __syncthreads();
        }
        if (i < n) rowptr[i + 1] = carry + sm[tid];
        __syncthreads();
        if (tid == 0) carry += sm[1023];
        __syncthreads();
    }
}
__global__ void copy_cursor_k(const int* __restrict__ rowptr, int* cursor, int n) {
    int i = blockIdx.x * blockDim.x + threadIdx.x;
    if (i < n) cursor[i] = rowptr[i];
}
__global__ void scatter_edges_k(const int* __restrict__ ei, int* cursor,
                                int* colv, int E) {
    int e = blockIdx.x * blockDim.x + threadIdx.x;
    if (e < E) {
        int s = ei[e];
        int d = ei[E + e];
        int pos = atomicAdd(&cursor[d], 1);
        colv[pos] = s;
    }
}
__global__ void scatter_loops_k(int* cursor, int* colv, int n) {
    int i = blockIdx.x * blockDim.x + threadIdx.x;
    if (i < n) {
        int pos = atomicAdd(&cursor[i], 1);
        colv[pos] = i;
    }
}

// ---------------------------------------------------------------------------
// Edge attention.  Block = (dst, head), 128 threads.  Head-major xl/xr (fp32).
// Writes per-head softmax-weighted sum into acc[h][n][c].
// ---------------------------------------------------------------------------
template <int NCH>
__global__ __launch_bounds__(128) void gat_edge_k(
    const float* __restrict__ xl, const float* __restrict__ xr,
    const float* __restrict__ att, const int* __restrict__ rowptr,
    const int* __restrict__ colv, float* __restrict__ accm,
    int C, int Nn)
{
    const int TPB = 128;
    int dst = blockIdx.x;
    int h = blockIdx.y;
    int tid = threadIdx.x;
    __shared__ float ws[2][4];

    const float* xlh = xl + (size_t)h * Nn * C;
    const float* xrh = xr + (size_t)h * Nn * C;

    float a[NCH], xd[NCH], acc[NCH];
#pragma unroll
    for (int j = 0; j < NCH; j++) {
        int c = tid + j * TPB;
        bool ok = (NCH * TPB == C) || (c < C);
        a[j]   = ok ? att[h * C + c] : 0.f;
        xd[j]  = ok ? xrh[(size_t)dst * C + c] : 0.f;
        acc[j] = 0.f;
    }

    float m = -3.4e38f, l = 0.f;
    int e0 = rowptr[dst], e1 = rowptr[dst + 1];
    for (int e = e0; e < e1; e++) {
        int s = __ldg(&colv[e]);
        const float* xsp = xlh + (size_t)s * C;
        float xs[NCH];
        float p = 0.f;
#pragma unroll
        for (int j = 0; j < NCH; j++) {
            int c = tid + j * TPB;
            float xv = ((NCH * TPB == C) || c < C) ? xsp[c] : 0.f;
            xs[j] = xv;
            float v = xv + xd[j];
            v = v > 0.f ? v : 0.2f * v;
            p += a[j] * v;
        }
#pragma unroll
        for (int o = 16; o > 0; o >>= 1) p += __shfl_xor_sync(0xffffffffu, p, o);
        int slot = e & 1;
        if ((tid & 31) == 0) ws[slot][tid >> 5] = p;
        __syncthreads();
        float ev = ws[slot][0] + ws[slot][1] + ws[slot][2] + ws[slot][3];

        float mn = fmaxf(m, ev);
        float sc = __expf(m - mn);
        float w  = __expf(ev - mn);
#pragma unroll
        for (int j = 0; j < NCH; j++) acc[j] = acc[j] * sc + w * xs[j];
        l = l * sc + w;
        m = mn;
    }

    float inv = 1.f / l;
    float* dstp = accm + ((size_t)h * Nn + dst) * C;
#pragma unroll
    for (int j = 0; j < NCH; j++) {
        int c = tid + j * TPB;
        if ((NCH * TPB == C) || c < C) dstp[c] = acc[j] * inv;
    }
}

// ---------------------------------------------------------------------------
// Head mean + bias + optional leaky; writes float (final) or half (next layer)
// ---------------------------------------------------------------------------
template <typename T>
__global__ void mean_bias_act_k(const float* __restrict__ accm,
                                const float* __restrict__ bias,
                                T* __restrict__ out,
                                int total, int C, size_t sliceN, int H,
                                float invH, float slope, int do_act) {
    int i = blockIdx.x * blockDim.x + threadIdx.x;
    if (i >= total) return;
    float s = 0.f;
    for (int h = 0; h < H; h++) s += accm[(size_t)h * sliceN + i];
    float v = s * invH + bias[i % C];
    if (do_act) v = v > 0.f ? v : slope * v;
    out[i] = (T)v;
}

// ---------------------------------------------------------------------------
// host orchestration
// ---------------------------------------------------------------------------
static void run_gemm(const __half* A, const __half* Bt, const float* bias,
                     float* C, int M, int K, int lda, int ldb, int Ncols, int Cdim) {
    dim3 grid((M + 127) / 128, Ncols / 128);
    gemm_h_k<<<grid, 128, GEMM_SMEM>>>(A, Bt, bias, C, M, K, lda, ldb, Ncols, Cdim);
}

template <typename TOUT>
static void run_layer(const __half* hin, int fi, int lda, int fo,
                      const float* Wl, const float* bl,
                      const float* Wr, const float* br,
                      const float* att, const float* bias,
                      float* xl, float* xr, float* accm,
                      __half* wlh, __half* wrh,
                      const int* rowptr, const int* colv,
                      TOUT* hout, int N, int H, bool act) {
    int Ncols = H * fo;
    int ldwt = (fi + 7) & ~7;
    {
        dim3 tb(32, 8);
        dim3 tg((Ncols + 31) / 32, (ldwt + 31) / 32);
        conv_trans_k<<<tg, tb>>>(Wl, wlh, fi, Ncols, ldwt);
        conv_trans_k<<<tg, tb>>>(Wr, wrh, fi, Ncols, ldwt);
    }
    run_gemm(hin, wlh, bl, xl, N, fi, lda, ldwt, Ncols, fo);
    run_gemm(hin, wrh, br, xr, N, fi, lda, ldwt, Ncols, fo);

    dim3 eg(N, H);
    if (fo == 128)
        gat_edge_k<1><<<eg, 128>>>(xl, xr, att, rowptr, colv, accm, fo, N);
    else if (fo == 512)
        gat_edge_k<4><<<eg, 128>>>(xl, xr, att, rowptr, colv, accm, fo, N);
    else
        gat_edge_k<9><<<eg, 128>>>(xl, xr, att, rowptr, colv, accm, fo, N);

    int total = N * fo;
    mean_bias_act_k<TOUT><<<(total + 255) / 256, 256>>>(
        accm, bias, hout, total, fo, (size_t)N * fo, H,
        1.f / (float)H, 0.01f, act ? 1 : 0);
}

extern "C" void kernel_launch(void* const* d_in, const int* in_sizes, int n_in,
                              void* d_out, int out_size) {
    const float* x  = (const float*)d_in[0];
    const int*   ei = (const int*)d_in[1];

    const float* W1l = (const float*)d_in[2];
    const float* b1l = (const float*)d_in[3];
    const float* W1r = (const float*)d_in[4];
    const float* b1r = (const float*)d_in[5];
    const float* at1 = (const float*)d_in[6];
    const float* bi1 = (const float*)d_in[7];
    const float* W2l = (const float*)d_in[8];
    const float* b2l = (const float*)d_in[9];
    const float* W2r = (const float*)d_in[10];
    const float* b2r = (const float*)d_in[11];
    const float* at2 = (const float*)d_in[12];
    const float* bi2 = (const float*)d_in[13];
    const float* W3l = (const float*)d_in[14];
    const float* b3l = (const float*)d_in[15];
    const float* W3r = (const float*)d_in[16];
    const float* b3r = (const float*)d_in[17];
    const float* at3 = (const float*)d_in[18];
    const float* bi3 = (const float*)d_in[19];

    int N = in_sizes[0] / 4;
    int E = in_sizes[1] / 2;
    int f1 = in_sizes[7];
    int f2 = in_sizes[13];
    int f3 = in_sizes[19];
    int H  = in_sizes[3] / f1;

    cudaFuncSetAttribute(gemm_h_k, cudaFuncAttributeMaxDynamicSharedMemorySize,
                         GEMM_SMEM);

    float *xl, *xr, *accm;
    __half *wlh, *wrh, *a0h, *h1h, *h2h;
    int *deg, *rowptr, *cursor, *colv;
    cudaGetSymbolAddress((void**)&xl, g_xl);
    cudaGetSymbolAddress((void**)&xr, g_xr);
    cudaGetSymbolAddress((void**)&accm, g_acc);
    cudaGetSymbolAddress((void**)&wlh, g_wlh);
    cudaGetSymbolAddress((void**)&wrh, g_wrh);
    cudaGetSymbolAddress((void**)&a0h, g_a0h);
    cudaGetSymbolAddress((void**)&h1h, g_h1h);
    cudaGetSymbolAddress((void**)&h2h, g_h2h);
    cudaGetSymbolAddress((void**)&deg, g_deg);
    cudaGetSymbolAddress((void**)&rowptr, g_rowptr);
    cudaGetSymbolAddress((void**)&cursor, g_cursor);
    cudaGetSymbolAddress((void**)&colv, g_col);

    // --- CSR build (by destination) ---
    init_deg_k<<<(N + 255) / 256, 256>>>(deg, N);
    count_deg_k<<<(E + 255) / 256, 256>>>(ei, deg, E);
    scan_rowptr_k<<<1, 1024>>>(deg, rowptr, N);
    copy_cursor_k<<<(N + 255) / 256, 256>>>(rowptr, cursor, N);
    scatter_edges_k<<<(E + 255) / 256, 256>>>(ei, cursor, colv, E);
    scatter_loops_k<<<(N + 255) / 256, 256>>>(cursor, colv, N);

    // --- x -> half (padded to 8 columns) ---
    conv_x_k<<<(N * 8 + 255) / 256, 256>>>(x, a0h, N, 4, 8);

    // --- 3 GATv2 layers ---
    run_layer<__half>(a0h, 4, 8, f1, W1l, b1l, W1r, b1r, at1, bi1,
                      xl, xr, accm, wlh, wrh, rowptr, colv, h1h, N, H, true);
    run_layer<__half>(h1h, f1, f1, f2, W2l, b2l, W2r, b2r, at2, bi2,
                      xl, xr, accm, wlh, wrh, rowptr, colv, h2h, N, H, true);
    run_layer<float>(h2h, f2, f2, f3, W3l, b3l, W3r, b3r, at3, bi3,
                     xl, xr, accm, wlh, wrh, rowptr, colv, (float*)d_out, N, H, false);
}